// round 4
// baseline (speedup 1.0000x reference)
#include <cuda_runtime.h>
#include <string.h>

// HyperConv2dDepthWise: per-batch-weight 5x5 depthwise conv + bias + SiLU
// input:  (16, 128, 128, 128) f32   -> 2048 planes of 128x128
// weights:(16, 3328) f32            -> per (b,c): 25 taps at b*3328+c*25, bias at b*3328+3200+c
// output: (16, 128, 128, 128) f32
//
// Round-3: horizontal f32x2 packing; aligned pairs via reinterpret (register
// aliasing, no MOV), only 3 odd-pair packs per row load. CTA = 64-row band,
// 256 threads, grid 4096. 5-row packed sliding register window per warp.

#define HW      128
#define BAND    64
#define SROWS   (BAND + 4)     // 68
#define SPITCH  136            // floats; logical col L lives at smem col L+4
#define WSTRIDE 3328           // 25*128 + 128
#define BOFF    3200           // 25*128

typedef unsigned long long ull;

__device__ __forceinline__ ull pair_of(float lo, float hi) {
    // Let the compiler place these; adjacent-register sources collapse to aliasing.
    float2 t = make_float2(lo, hi);
    ull r;
    memcpy(&r, &t, 8);
    return r;
}
__device__ __forceinline__ void fma2(ull& d, ull a, ull b) {
    asm("fma.rn.f32x2 %0, %1, %2, %0;" : "+l"(d) : "l"(a), "l"(b));
}
__device__ __forceinline__ float2 unpk(ull v) {
    float2 f;
    memcpy(&f, &v, 8);
    return f;
}
__device__ __forceinline__ float silu_f(float x) {
    return __fdividef(x, 1.0f + __expf(-x));
}

// One packed window row: covers logical cols x0-2 .. x0+5.
// E0=(x-2,x-1) E1=(x,x+1) E2=(x+2,x+3) E3=(x+4,x+5)  <- aligned halves, free
// O0=(x-1,x)   O1=(x+1,x+2) O2=(x+3,x+4)             <- 3 real packs per row
struct WRow {
    ull E0, E1, E2, E3, O0, O1, O2;
};

__device__ __forceinline__ WRow load_row(const float* __restrict__ p) {
    // p = &smem[row][x0]  (smem col x0 == logical col x0-4), 16B aligned
    float4 A = *(const float4*)(p);      // logical x0-4 .. x0-1
    float4 B = *(const float4*)(p + 4);  // logical x0   .. x0+3
    float4 C = *(const float4*)(p + 8);  // logical x0+4 .. x0+7
    WRow r;
    // aligned pairs: adjacent components of the same float4 -> register pairs
    memcpy(&r.E0, &A.z, 8);
    memcpy(&r.E1, &B.x, 8);
    memcpy(&r.E2, &B.z, 8);
    memcpy(&r.E3, &C.x, 8);
    // odd-phase pairs: genuine cross-register packs (2 MOVs each, 3 per row)
    r.O0 = pair_of(A.w, B.x);
    r.O1 = pair_of(B.y, B.z);
    r.O2 = pair_of(B.w, C.x);
    return r;
}

__global__ __launch_bounds__(256, 3)
void hconv_dw_kernel(const float* __restrict__ input,
                     const float* __restrict__ wts,
                     float* __restrict__ out)
{
    __shared__ float smem[SROWS * SPITCH];

    const int bid   = blockIdx.x;
    const int band  = bid & 1;          // 2 bands of 64 rows per plane
    const int plane = bid >> 1;         // b*128 + c
    const int b     = plane >> 7;
    const int c     = plane & 127;
    const int r0    = band * BAND;

    const float* __restrict__ ip = input + (size_t)plane * (HW * HW);
    float* __restrict__ op       = out   + (size_t)plane * (HW * HW);

    const int tid = threadIdx.x;

    // ---- stage band (+2-row halo) into zero-padded smem ----
    // smem row y holds global row (r0 + y - 2); interior cols 4..131.
    {
        const int lq = tid & 31;        // interior quad: logical col lq*4
        const int lr = tid >> 5;        // 0..7
        const float4 z4 = make_float4(0.f, 0.f, 0.f, 0.f);
#pragma unroll
        for (int k = 0; k < 9; k++) {
            const int y = lr + k * 8;   // 0..71
            if (y < SROWS) {
                const int g = r0 + y - 2;
                float4 v = z4;
                if (g >= 0 && g < HW)
                    v = *(const float4*)(ip + g * HW + lq * 4);
                *(float4*)(smem + y * SPITCH + 4 + lq * 4) = v;
            }
        }
        // zero halo columns: smem quads 0 and 33, all 68 rows (136 stores)
        if (tid < 2 * SROWS) {
            const int y = tid >> 1;
            const int q = (tid & 1) ? 33 : 0;
            *(float4*)(smem + y * SPITCH + q * 4) = z4;
        }
    }

    // ---- per-plane weights: 25 taps packed (w,w) + bias ----
    const float* wp = wts + b * WSTRIDE + c * 25;
    ull w2[25];
#pragma unroll
    for (int t = 0; t < 25; t++) {
        const float w = __ldg(wp + t);
        w2[t] = pair_of(w, w);
    }
    const float bias = __ldg(wts + b * WSTRIDE + BOFF + c);
    const ull bias2 = pair_of(bias, bias);

    __syncthreads();

    // ---- compute: warp = full row width, 32 lanes x 4 cols ----
    const int warp = tid >> 5;          // 0..7
    const int lane = tid & 31;
    const int x0   = lane * 4;          // logical output col base
    const int br0  = warp * 8;          // band-local first output row

    // warp needs smem rows br0 .. br0+11 (global rows r0+br0-2 .. r0+br0+9)
    WRow win[5];
#pragma unroll
    for (int y = 0; y < 4; y++)
        win[y] = load_row(smem + (br0 + y) * SPITCH + x0);

#pragma unroll
    for (int i = 0; i < 8; i++) {
        // load the new bottom row into ring slot (i+4)%5; it is consumed by
        // weight row d=4 (last), so 40 FFMA2 hide the LDS latency.
        win[(i + 4) % 5] = load_row(smem + (br0 + i + 4) * SPITCH + x0);

        ull acc0 = bias2, acc1 = bias2;
#pragma unroll
        for (int d = 0; d < 5; d++) {
            const WRow& r = win[(i + d) % 5];
            fma2(acc0, w2[d * 5 + 0], r.E0);  fma2(acc1, w2[d * 5 + 0], r.E1);
            fma2(acc0, w2[d * 5 + 1], r.O0);  fma2(acc1, w2[d * 5 + 1], r.O1);
            fma2(acc0, w2[d * 5 + 2], r.E1);  fma2(acc1, w2[d * 5 + 2], r.E2);
            fma2(acc0, w2[d * 5 + 3], r.O1);  fma2(acc1, w2[d * 5 + 3], r.O2);
            fma2(acc0, w2[d * 5 + 4], r.E2);  fma2(acc1, w2[d * 5 + 4], r.E3);
        }

        // epilogue: SiLU + coalesced float4 store
        const float2 a  = unpk(acc0);
        const float2 bb = unpk(acc1);
        float4 o = make_float4(silu_f(a.x), silu_f(a.y), silu_f(bb.x), silu_f(bb.y));
        *(float4*)(op + (r0 + br0 + i) * HW + x0) = o;
    }
}

extern "C" void kernel_launch(void* const* d_in, const int* in_sizes, int n_in,
                              void* d_out, int out_size)
{
    const float* input = (const float*)d_in[0];
    const float* wts   = (const float*)d_in[1];
    float* out         = (float*)d_out;

    // 2048 planes x 2 bands of 64 rows
    hconv_dw_kernel<<<4096, 256>>>(input, wts, out);
}

// round 6
// speedup vs baseline: 1.0930x; 1.0930x over previous
#include <cuda_runtime.h>
#include <string.h>

// HyperConv2dDepthWise: per-batch-weight 5x5 depthwise conv + bias + SiLU
// input:  (16, 128, 128, 128) f32   -> 2048 planes of 128x128
// weights:(16, 3328) f32            -> per (b,c): 25 taps at b*3328+c*25, bias at b*3328+3200+c
// output: (16, 128, 128, 128) f32
//
// Round-4: R2 geometry (BAND=32, 128 thr, grid 8192 — fastest measured) +
// packed-f32x2 SiLU epilogue via tanh.approx.f32:
//   silu(x) = h*(1+tanh(h)), h = x/2  ->  mul.f32x2 + 2x tanh + fma.f32x2
// cutting the epilogue from ~24 to 8 instructions per output row.

#define HW      128
#define BAND    32
#define SROWS   (BAND + 4)     // 36
#define SPITCH  136            // floats; logical col L lives at smem col L+4
#define WSTRIDE 3328           // 25*128 + 128
#define BOFF    3200           // 25*128

typedef unsigned long long ull;

__device__ __forceinline__ ull pair_of(float lo, float hi) {
    float2 t = make_float2(lo, hi);
    ull r;
    memcpy(&r, &t, 8);
    return r;
}
__device__ __forceinline__ void fma2(ull& d, ull a, ull b) {
    asm("fma.rn.f32x2 %0, %1, %2, %0;" : "+l"(d) : "l"(a), "l"(b));
}
__device__ __forceinline__ float2 unpk(ull v) {
    float2 f;
    memcpy(&f, &v, 8);
    return f;
}

// packed SiLU: silu(x) = h + h*tanh(h), h = 0.5*x   (exact identity; tanh.approx HW op)
__device__ __forceinline__ ull silu2(ull acc, ull half2c) {
    ull h2;
    asm("mul.rn.f32x2 %0, %1, %2;" : "=l"(h2) : "l"(acc), "l"(half2c));
    float2 h = unpk(h2);
    float t0, t1;
    asm("tanh.approx.f32 %0, %1;" : "=f"(t0) : "f"(h.x));
    asm("tanh.approx.f32 %0, %1;" : "=f"(t1) : "f"(h.y));
    ull t2 = pair_of(t0, t1);
    ull r;
    asm("fma.rn.f32x2 %0, %1, %2, %1;" : "=l"(r) : "l"(h2), "l"(t2));
    return r;
}

// One packed window row: covers logical cols x0-2 .. x0+5.
// E0=(x-2,x-1) E1=(x,x+1) E2=(x+2,x+3) E3=(x+4,x+5)  <- aligned halves
// O0=(x-1,x)   O1=(x+1,x+2) O2=(x+3,x+4)             <- 3 cross-register packs
struct WRow {
    ull E0, E1, E2, E3, O0, O1, O2;
};

__device__ __forceinline__ WRow load_row(const float* __restrict__ p) {
    // p = &smem[row][x0]  (smem col x0 == logical col x0-4), 16B aligned
    float4 A = *(const float4*)(p);      // logical x0-4 .. x0-1
    float4 B = *(const float4*)(p + 4);  // logical x0   .. x0+3
    float4 C = *(const float4*)(p + 8);  // logical x0+4 .. x0+7
    WRow r;
    memcpy(&r.E0, &A.z, 8);
    memcpy(&r.E1, &B.x, 8);
    memcpy(&r.E2, &B.z, 8);
    memcpy(&r.E3, &C.x, 8);
    r.O0 = pair_of(A.w, B.x);
    r.O1 = pair_of(B.y, B.z);
    r.O2 = pair_of(B.w, C.x);
    return r;
}

__global__ __launch_bounds__(128, 3)
void hconv_dw_kernel(const float* __restrict__ input,
                     const float* __restrict__ wts,
                     float* __restrict__ out)
{
    __shared__ float smem[SROWS * SPITCH];

    const int bid   = blockIdx.x;
    const int band  = bid & 3;          // 4 bands of 32 rows per plane
    const int plane = bid >> 2;         // b*128 + c
    const int b     = plane >> 7;
    const int c     = plane & 127;
    const int r0    = band * BAND;

    const float* __restrict__ ip = input + (size_t)plane * (HW * HW);
    float* __restrict__ op       = out   + (size_t)plane * (HW * HW);

    const int tid = threadIdx.x;

    // ---- stage band (+2-row halo) into zero-padded smem ----
    // smem row y holds global row (r0 + y - 2); interior cols 4..131.
    {
        const int lq = tid & 31;        // interior quad: logical col lq*4
        const int lr = tid >> 5;        // 0..3
        const float4 z4 = make_float4(0.f, 0.f, 0.f, 0.f);
#pragma unroll
        for (int k = 0; k < 9; k++) {
            const int y = lr + k * 4;   // 0..35
            const int g = r0 + y - 2;
            float4 v = z4;
            if (g >= 0 && g < HW)
                v = *(const float4*)(ip + g * HW + lq * 4);
            *(float4*)(smem + y * SPITCH + 4 + lq * 4) = v;
        }
        // zero halo columns: smem quads 0 and 33, all 36 rows (72 stores)
        if (tid < 2 * SROWS) {
            const int y = tid >> 1;
            const int q = (tid & 1) ? 33 : 0;
            *(float4*)(smem + y * SPITCH + q * 4) = z4;
        }
    }

    // ---- per-plane weights: 25 taps packed (w,w) + bias ----
    const float* wp = wts + b * WSTRIDE + c * 25;
    ull w2[25];
#pragma unroll
    for (int t = 0; t < 25; t++) {
        const float w = __ldg(wp + t);
        w2[t] = pair_of(w, w);
    }
    const float bias = __ldg(wts + b * WSTRIDE + BOFF + c);
    const ull bias2 = pair_of(bias, bias);
    const ull half2c = pair_of(0.5f, 0.5f);

    __syncthreads();

    // ---- compute: warp = full row width, 32 lanes x 4 cols ----
    const int warp = tid >> 5;          // 0..3
    const int lane = tid & 31;
    const int x0   = lane * 4;          // logical output col base
    const int br0  = warp * 8;          // band-local first output row

    // warp needs smem rows br0 .. br0+11 (global rows r0+br0-2 .. r0+br0+9)
    WRow win[5];
#pragma unroll
    for (int y = 0; y < 4; y++)
        win[y] = load_row(smem + (br0 + y) * SPITCH + x0);

    float* outp = op + (r0 + br0) * HW + x0;

#pragma unroll
    for (int i = 0; i < 8; i++) {
        // load the new bottom row into ring slot (i+4)%5; it is consumed by
        // weight row d=4 (last), so 40 FFMA2 hide the LDS latency.
        win[(i + 4) % 5] = load_row(smem + (br0 + i + 4) * SPITCH + x0);

        ull acc0 = bias2, acc1 = bias2;
#pragma unroll
        for (int d = 0; d < 5; d++) {
            const WRow& r = win[(i + d) % 5];
            fma2(acc0, w2[d * 5 + 0], r.E0);  fma2(acc1, w2[d * 5 + 0], r.E1);
            fma2(acc0, w2[d * 5 + 1], r.O0);  fma2(acc1, w2[d * 5 + 1], r.O1);
            fma2(acc0, w2[d * 5 + 2], r.E1);  fma2(acc1, w2[d * 5 + 2], r.E2);
            fma2(acc0, w2[d * 5 + 3], r.O1);  fma2(acc1, w2[d * 5 + 3], r.O2);
            fma2(acc0, w2[d * 5 + 4], r.E2);  fma2(acc1, w2[d * 5 + 4], r.E3);
        }

        // epilogue: packed SiLU + coalesced float4 store
        const ull s0 = silu2(acc0, half2c);
        const ull s1 = silu2(acc1, half2c);
        float4 o;
        memcpy(&o.x, &s0, 8);
        memcpy(&o.z, &s1, 8);
        *(float4*)(outp) = o;
        outp += HW;
    }
}

extern "C" void kernel_launch(void* const* d_in, const int* in_sizes, int n_in,
                              void* d_out, int out_size)
{
    const float* input = (const float*)d_in[0];
    const float* wts   = (const float*)d_in[1];
    float* out         = (float*)d_out;

    // 2048 planes x 4 bands of 32 rows
    hconv_dw_kernel<<<8192, 128>>>(input, wts, out);
}